// round 1
// baseline (speedup 1.0000x reference)
#include <cuda_runtime.h>
#include <cuda_bf16.h>
#include <math.h>

// Problem constants
#define BB   32
#define TT   127
#define SS   256
#define HH   512
#define VV   8000
#define NHH  8
#define HDD  64
#define BT   (BB*TT)      // 4064
#define BS   (BB*SS)      // 8192

// ---------------- scratch (device globals; no allocations allowed) ----------------
__device__ float g_emb [BT * HH];        // embedded targets
__device__ float g_xg  [BT * 4 * HH];    // precomputed input gates
__device__ float g_h   [2][BB * HH];     // ping-pong hidden state
__device__ float g_c   [BB * HH];        // cell state
__device__ float g_lstm[BT * HH];        // lstm outputs
__device__ float g_q   [BT * HH];
__device__ float g_k   [BS * HH];
__device__ float g_v   [BS * HH];
__device__ float g_ctx [BT * HH];
__device__ float g_comb[BT * HH];

// ---------------- init: zero h0 and c ----------------
__global__ void zero_kernel(float* a, float* b, int n) {
    int i = blockIdx.x * blockDim.x + threadIdx.x;
    if (i < n) { a[i] = 0.f; b[i] = 0.f; }
}

// ---------------- embedding gather ----------------
__global__ void gather_kernel(const int* __restrict__ targets,
                              const float* __restrict__ table,
                              float* __restrict__ out) {
    int bt = blockIdx.x;                 // 0..4063
    int b = bt / TT, t = bt - b * TT;
    int tok = targets[b * 128 + t];      // targets is [B,128], use [:, :-1]
    const float4* src = (const float4*)(table + (size_t)tok * HH);
    float4* dst = (float4*)(out + (size_t)bt * HH);
    dst[threadIdx.x] = src[threadIdx.x]; // 128 threads * float4 = 512 floats
}

// ---------------- generic SGEMM: C[M,N] = A[M,K] @ B[N,K]^T + bias1 + bias2 + res ----------------
__global__ __launch_bounds__(256) void sgemm_kernel(
    const float* __restrict__ A, const float* __restrict__ B,
    const float* __restrict__ bias1, const float* __restrict__ bias2,
    const float* __restrict__ res, float* __restrict__ C,
    int M, int N, int K)
{
    __shared__ float As[8][128];
    __shared__ float Bs[8][128];
    const int bm = blockIdx.y * 128;
    const int bn = blockIdx.x * 128;
    const int tid = threadIdx.x;
    const int lr = tid >> 1;            // 0..127 (load row)
    const int lc = (tid & 1) << 2;      // 0 or 4 (load col group)
    const int tx = tid & 15;            // n-tile
    const int ty = tid >> 4;            // m-tile

    float acc[8][8];
    #pragma unroll
    for (int i = 0; i < 8; i++)
        #pragma unroll
        for (int j = 0; j < 8; j++) acc[i][j] = 0.f;

    const bool aval = (bm + lr) < M;
    const bool bval = (bn + lr) < N;
    const float* Aptr = A + (size_t)(bm + lr) * K + lc;
    const float* Bptr = B + (size_t)(bn + lr) * K + lc;
    const float4 zero4 = make_float4(0.f, 0.f, 0.f, 0.f);

    for (int k0 = 0; k0 < K; k0 += 8) {
        float4 a4 = aval ? *(const float4*)(Aptr + k0) : zero4;
        float4 b4 = bval ? *(const float4*)(Bptr + k0) : zero4;
        As[lc + 0][lr] = a4.x; As[lc + 1][lr] = a4.y;
        As[lc + 2][lr] = a4.z; As[lc + 3][lr] = a4.w;
        Bs[lc + 0][lr] = b4.x; Bs[lc + 1][lr] = b4.y;
        Bs[lc + 2][lr] = b4.z; Bs[lc + 3][lr] = b4.w;
        __syncthreads();
        #pragma unroll
        for (int kk = 0; kk < 8; kk++) {
            float ra[8], rb[8];
            *(float4*)(ra)     = *(const float4*)(&As[kk][ty * 8]);
            *(float4*)(ra + 4) = *(const float4*)(&As[kk][ty * 8 + 4]);
            *(float4*)(rb)     = *(const float4*)(&Bs[kk][tx * 8]);
            *(float4*)(rb + 4) = *(const float4*)(&Bs[kk][tx * 8 + 4]);
            #pragma unroll
            for (int i = 0; i < 8; i++)
                #pragma unroll
                for (int j = 0; j < 8; j++)
                    acc[i][j] += ra[i] * rb[j];
        }
        __syncthreads();
    }

    #pragma unroll
    for (int i = 0; i < 8; i++) {
        int row = bm + ty * 8 + i;
        if (row >= M) continue;
        #pragma unroll
        for (int j = 0; j < 8; j++) {
            int col = bn + tx * 8 + j;
            if (col >= N) continue;
            float v = acc[i][j];
            if (bias1) v += bias1[col];
            if (bias2) v += bias2[col];
            if (res)   v += res[(size_t)row * N + col];
            C[(size_t)row * N + col] = v;
        }
    }
}

// ---------------- LSTM step: gates = xg[:,t,:] + h_prev @ w_hh^T, activations, update ----------------
// 128 blocks, block j owns h-columns [4j, 4j+4) -> gate rows {q*512 + c : q in 0..3}.
// 128 threads; microtile 2 batches x 2 gate-cols.
#define HP 516   // h smem pitch (mult of 4 for float4 stores)
#define WP 514   // w smem pitch (conflict-friendly for stride-2-row reads)
__global__ __launch_bounds__(128) void lstm_step_kernel(
    const float* __restrict__ xg, const float* __restrict__ w_hh,
    const float* __restrict__ h_prev, float* __restrict__ h_next,
    float* __restrict__ c_state, float* __restrict__ lstm_out, int t)
{
    extern __shared__ float smem[];
    float* h_sm = smem;                    // 32 * HP
    float* w_sm = smem + 32 * HP;          // 16 * WP
    float* g_sm = w_sm + 16 * WP;          // 16 * 33

    const int tid = threadIdx.x;
    const int c0  = blockIdx.x * 4;

    // load h_prev [32,512] -> smem
    for (int idx = tid; idx < 32 * 128; idx += 128) {
        int b = idx >> 7; int k4 = (idx & 127) << 2;
        float4 v = *(const float4*)(h_prev + b * HH + k4);
        float* d = h_sm + b * HP + k4;
        d[0] = v.x; d[1] = v.y; d[2] = v.z; d[3] = v.w;
    }
    // load 16 w_hh rows (4 gates x 4 cols) -> smem
    for (int idx = tid; idx < 16 * 128; idx += 128) {
        int r = idx >> 7; int k4 = (idx & 127) << 2;
        int gr = (r >> 2) * HH + c0 + (r & 3);
        float4 v = *(const float4*)(w_hh + (size_t)gr * HH + k4);
        float* d = w_sm + r * WP + k4;
        d[0] = v.x; d[1] = v.y; d[2] = v.z; d[3] = v.w;
    }
    __syncthreads();

    const int cp = tid & 7;   // col pair 0..7 -> local cols 2cp, 2cp+1
    const int bp = tid >> 3;  // batch pair 0..15 -> batches 2bp, 2bp+1
    const float* h0 = h_sm + (2 * bp) * HP;
    const float* h1 = h_sm + (2 * bp + 1) * HP;
    const float* w0 = w_sm + (2 * cp) * WP;
    const float* w1 = w_sm + (2 * cp + 1) * WP;
    float a00 = 0.f, a01 = 0.f, a10 = 0.f, a11 = 0.f;
    #pragma unroll 8
    for (int k = 0; k < HH; k++) {
        float hv0 = h0[k], hv1 = h1[k];
        float wv0 = w0[k], wv1 = w1[k];
        a00 += hv0 * wv0; a01 += hv0 * wv1;
        a10 += hv1 * wv0; a11 += hv1 * wv1;
    }

    const int lc0 = 2 * cp, lc1 = lc0 + 1;
    const int b0 = 2 * bp,  b1 = b0 + 1;
    const int col0 = (lc0 >> 2) * HH + c0 + (lc0 & 3);
    const int col1 = (lc1 >> 2) * HH + c0 + (lc1 & 3);
    const size_t xr0 = (size_t)(b0 * TT + t) * (4 * HH);
    const size_t xr1 = (size_t)(b1 * TT + t) * (4 * HH);
    g_sm[lc0 * 33 + b0] = a00 + xg[xr0 + col0];
    g_sm[lc1 * 33 + b0] = a01 + xg[xr0 + col1];
    g_sm[lc0 * 33 + b1] = a10 + xg[xr1 + col0];
    g_sm[lc1 * 33 + b1] = a11 + xg[xr1 + col1];
    __syncthreads();

    // activation + state update: 128 threads = 4 cols x 32 batches
    const int cc = tid >> 5, b = tid & 31;
    float iv = g_sm[(cc)      * 33 + b];
    float fv = g_sm[(4 + cc)  * 33 + b];
    float gv = g_sm[(8 + cc)  * 33 + b];
    float ov = g_sm[(12 + cc) * 33 + b];
    const int hcol = c0 + cc;
    float cold = c_state[b * HH + hcol];
    float ig = 1.f / (1.f + __expf(-iv));
    float fg = 1.f / (1.f + __expf(-fv));
    float og = 1.f / (1.f + __expf(-ov));
    float gg = tanhf(gv);
    float cn = fg * cold + ig * gg;
    float hn = og * tanhf(cn);
    c_state[b * HH + hcol] = cn;
    h_next[b * HH + hcol]  = hn;
    lstm_out[(size_t)(b * TT + t) * HH + hcol] = hn;
}

// ---------------- fused attention: per (t-chunk, head, batch) ----------------
#define KTP 257   // transposed K/V pitch (257 mod 32 == 1 -> conflict-free lane stride)
#define QSP 68
#define PSP 260
__global__ __launch_bounds__(256) void attn_kernel(
    const float* __restrict__ q, const float* __restrict__ kmat,
    const float* __restrict__ vmat, float* __restrict__ ctx)
{
    extern __shared__ float smem[];
    float* Kt   = smem;                    // [64][KTP]
    float* Vt   = Kt + 64 * KTP;           // [64][KTP]
    float* qs   = Vt + 64 * KTP;           // [32][QSP]
    float* ps   = qs + 32 * QSP;           // [32][PSP]
    float* sums = ps + 32 * PSP;           // [32]

    const int t0 = blockIdx.x * 32;
    const int h  = blockIdx.y;
    const int b  = blockIdx.z;
    const int tid = threadIdx.x;

    // load K,V transposed: Kt[d][s] = K[b*256+s][h*64+d]
    for (int idx = tid; idx < 256 * 16; idx += 256) {
        int s = idx >> 4; int d4 = (idx & 15) << 2;
        size_t off = (size_t)(b * SS + s) * HH + h * HDD + d4;
        float4 kv = *(const float4*)(kmat + off);
        Kt[(d4 + 0) * KTP + s] = kv.x; Kt[(d4 + 1) * KTP + s] = kv.y;
        Kt[(d4 + 2) * KTP + s] = kv.z; Kt[(d4 + 3) * KTP + s] = kv.w;
        float4 vv = *(const float4*)(vmat + off);
        Vt[(d4 + 0) * KTP + s] = vv.x; Vt[(d4 + 1) * KTP + s] = vv.y;
        Vt[(d4 + 2) * KTP + s] = vv.z; Vt[(d4 + 3) * KTP + s] = vv.w;
    }
    // load q chunk
    for (int idx = tid; idx < 32 * 16; idx += 256) {
        int r = idx >> 4; int d4 = (idx & 15) << 2;
        int trow = t0 + r;
        float4 qv = make_float4(0.f, 0.f, 0.f, 0.f);
        if (trow < TT)
            qv = *(const float4*)(q + (size_t)(b * TT + trow) * HH + h * HDD + d4);
        float* d = qs + r * QSP + d4;
        d[0] = qv.x; d[1] = qv.y; d[2] = qv.z; d[3] = qv.w;
    }
    __syncthreads();

    const int r  = tid >> 3;  // query row in chunk
    const int lc = tid & 7;   // lane-col

    float qreg[64];
    #pragma unroll
    for (int d = 0; d < 64; d++) qreg[d] = qs[r * QSP + d];

    float sc[32];
    for (int si = 0; si < 32; si++) {
        int s = si * 8 + lc;
        float acc = 0.f;
        #pragma unroll
        for (int d = 0; d < 64; d++) acc += qreg[d] * Kt[d * KTP + s];
        sc[si] = acc * 0.125f;   // 1/sqrt(64)
    }
    float m = -1e30f;
    #pragma unroll
    for (int si = 0; si < 32; si++) m = fmaxf(m, sc[si]);
    m = fmaxf(m, __shfl_xor_sync(0xffffffff, m, 1));
    m = fmaxf(m, __shfl_xor_sync(0xffffffff, m, 2));
    m = fmaxf(m, __shfl_xor_sync(0xffffffff, m, 4));
    float ssum = 0.f;
    #pragma unroll
    for (int si = 0; si < 32; si++) {
        float e = __expf(sc[si] - m);
        ssum += e;
        ps[r * PSP + si * 8 + lc] = e;
    }
    ssum += __shfl_xor_sync(0xffffffff, ssum, 1);
    ssum += __shfl_xor_sync(0xffffffff, ssum, 2);
    ssum += __shfl_xor_sync(0xffffffff, ssum, 4);
    if (lc == 0) sums[r] = ssum;
    __syncthreads();

    // ctx: thread covers d = lc + 8j
    float accv[8];
    #pragma unroll
    for (int j = 0; j < 8; j++) accv[j] = 0.f;
    const float* prow = ps + r * PSP;
    #pragma unroll 4
    for (int s = 0; s < 256; s++) {
        float pv = prow[s];
        #pragma unroll
        for (int j = 0; j < 8; j++)
            accv[j] += pv * Vt[(lc + 8 * j) * KTP + s];
    }
    float inv = 1.0f / sums[r];
    int trow = t0 + r;
    if (trow < TT) {
        float* dst = ctx + (size_t)(b * TT + trow) * HH + h * HDD;
        #pragma unroll
        for (int j = 0; j < 8; j++) dst[lc + 8 * j] = accv[j] * inv;
    }
}

// ---------------- launch ----------------
extern "C" void kernel_launch(void* const* d_in, const int* in_sizes, int n_in,
                              void* d_out, int out_size) {
    const int*   targets  = (const int*)  d_in[0];
    const float* enc      = (const float*)d_in[1];
    const float* embedding= (const float*)d_in[2];
    const float* w_ih     = (const float*)d_in[3];
    const float* w_hh     = (const float*)d_in[4];
    const float* b_ih     = (const float*)d_in[5];
    const float* b_hh     = (const float*)d_in[6];
    const float* in_proj_w= (const float*)d_in[7];
    const float* in_proj_b= (const float*)d_in[8];
    const float* out_proj_w=(const float*)d_in[9];
    const float* out_proj_b=(const float*)d_in[10];
    const float* fc_w     = (const float*)d_in[11];
    const float* fc_b     = (const float*)d_in[12];
    float* out = (float*)d_out;

    float *p_emb, *p_xg, *p_h, *p_c, *p_lstm, *p_q, *p_k, *p_v, *p_ctx, *p_comb;
    cudaGetSymbolAddress((void**)&p_emb,  g_emb);
    cudaGetSymbolAddress((void**)&p_xg,   g_xg);
    cudaGetSymbolAddress((void**)&p_h,    g_h);
    cudaGetSymbolAddress((void**)&p_c,    g_c);
    cudaGetSymbolAddress((void**)&p_lstm, g_lstm);
    cudaGetSymbolAddress((void**)&p_q,    g_q);
    cudaGetSymbolAddress((void**)&p_k,    g_k);
    cudaGetSymbolAddress((void**)&p_v,    g_v);
    cudaGetSymbolAddress((void**)&p_ctx,  g_ctx);
    cudaGetSymbolAddress((void**)&p_comb, g_comb);
    float* h_buf0 = p_h;
    float* h_buf1 = p_h + BB * HH;

    const int lstm_smem = (32 * HP + 16 * WP + 16 * 33) * (int)sizeof(float);
    const int attn_smem = (64 * KTP * 2 + 32 * QSP + 32 * PSP + 32) * (int)sizeof(float);
    cudaFuncSetAttribute(lstm_step_kernel, cudaFuncAttributeMaxDynamicSharedMemorySize, lstm_smem);
    cudaFuncSetAttribute(attn_kernel,      cudaFuncAttributeMaxDynamicSharedMemorySize, attn_smem);

    // 1. zero h0, c
    zero_kernel<<<(BB * HH + 255) / 256, 256>>>(h_buf0, p_c, BB * HH);

    // 2. gather embeddings
    gather_kernel<<<BT, 128>>>(targets, embedding, p_emb);

    // 3. xg = emb @ w_ih^T + b_ih + b_hh   [4064, 2048]
    {
        dim3 grid((4 * HH + 127) / 128, (BT + 127) / 128);
        sgemm_kernel<<<grid, 256>>>(p_emb, w_ih, b_ih, b_hh, nullptr, p_xg, BT, 4 * HH, HH);
    }

    // 4. LSTM recurrence
    for (int t = 0; t < TT; t++) {
        float* hp = (t & 1) ? h_buf1 : h_buf0;
        float* hn = (t & 1) ? h_buf0 : h_buf1;
        lstm_step_kernel<<<128, 128, lstm_smem>>>(p_xg, w_hh, hp, hn, p_c, p_lstm, t);
    }

    // 5. q/k/v projections
    {
        dim3 gq((HH + 127) / 128, (BT + 127) / 128);
        sgemm_kernel<<<gq, 256>>>(p_lstm, in_proj_w, in_proj_b, nullptr, nullptr, p_q, BT, HH, HH);
        dim3 gk((HH + 127) / 128, (BS + 127) / 128);
        sgemm_kernel<<<gk, 256>>>(enc, in_proj_w + (size_t)HH * HH, in_proj_b + HH,
                                  nullptr, nullptr, p_k, BS, HH, HH);
        sgemm_kernel<<<gk, 256>>>(enc, in_proj_w + (size_t)2 * HH * HH, in_proj_b + 2 * HH,
                                  nullptr, nullptr, p_v, BS, HH, HH);
    }

    // 6. fused attention -> ctx
    {
        dim3 grid(4, NHH, BB);
        attn_kernel<<<grid, 256, attn_smem>>>(p_q, p_k, p_v, p_ctx);
    }

    // 7. combined = ctx @ out_proj^T + out_proj_b + lstm_out
    {
        dim3 grid((HH + 127) / 128, (BT + 127) / 128);
        sgemm_kernel<<<grid, 256>>>(p_ctx, out_proj_w, out_proj_b, nullptr, p_lstm, p_comb, BT, HH, HH);
    }

    // 8. out = combined @ fc_w^T + fc_b   [4064, 8000]
    {
        dim3 grid((VV + 127) / 128, (BT + 127) / 128);
        sgemm_kernel<<<grid, 256>>>(p_comb, fc_w, fc_b, nullptr, nullptr, out, BT, VV, HH);
    }
}

// round 2
// speedup vs baseline: 1.3008x; 1.3008x over previous
#include <cuda_runtime.h>
#include <cuda_bf16.h>
#include <math.h>

// Problem constants
#define BB   32
#define TT   127
#define SS   256
#define HH   512
#define VV   8000
#define NHH  8
#define HDD  64
#define BT   (BB*TT)      // 4064
#define BS   (BB*SS)      // 8192
#define NBLK 128          // persistent LSTM grid (must all be co-resident)

// ---------------- scratch (device globals; no allocations allowed) ----------------
__device__ float g_emb [BT * HH];        // embedded targets
__device__ float g_xg  [BT * 4 * HH];    // precomputed input gates
__device__ float g_h   [2][BB * HH];     // ping-pong hidden state
__device__ float g_lstm[BT * HH];        // lstm outputs
__device__ float g_q   [BT * HH];
__device__ float g_k   [BS * HH];
__device__ float g_v   [BS * HH];
__device__ float g_ctx [BT * HH];
__device__ float g_comb[BT * HH];
__device__ volatile unsigned g_bar;      // grid barrier counter

// ---------------- init: zero h0 and barrier ----------------
__global__ void zero_kernel(float* h0, int n) {
    int i = blockIdx.x * blockDim.x + threadIdx.x;
    if (i < n) h0[i] = 0.f;
    if (i == 0) g_bar = 0u;
}

// ---------------- embedding gather ----------------
__global__ void gather_kernel(const int* __restrict__ targets,
                              const float* __restrict__ table,
                              float* __restrict__ out) {
    int bt = blockIdx.x;                 // 0..4063
    int b = bt / TT, t = bt - b * TT;
    int tok = targets[b * 128 + t];      // targets is [B,128], use [:, :-1]
    const float4* src = (const float4*)(table + (size_t)tok * HH);
    float4* dst = (float4*)(out + (size_t)bt * HH);
    dst[threadIdx.x] = src[threadIdx.x]; // 128 threads * float4 = 512 floats
}

// ---------------- generic SGEMM: C[M,N] = A[M,K] @ B[N,K]^T + bias1 + bias2 + res ----------------
__global__ __launch_bounds__(256) void sgemm_kernel(
    const float* __restrict__ A, const float* __restrict__ B,
    const float* __restrict__ bias1, const float* __restrict__ bias2,
    const float* __restrict__ res, float* __restrict__ C,
    int M, int N, int K)
{
    __shared__ float As[8][128];
    __shared__ float Bs[8][128];
    const int bm = blockIdx.y * 128;
    const int bn = blockIdx.x * 128;
    const int tid = threadIdx.x;
    const int lr = tid >> 1;            // 0..127 (load row)
    const int lc = (tid & 1) << 2;      // 0 or 4 (load col group)
    const int tx = tid & 15;            // n-tile
    const int ty = tid >> 4;            // m-tile

    float acc[8][8];
    #pragma unroll
    for (int i = 0; i < 8; i++)
        #pragma unroll
        for (int j = 0; j < 8; j++) acc[i][j] = 0.f;

    const bool aval = (bm + lr) < M;
    const bool bval = (bn + lr) < N;
    const float* Aptr = A + (size_t)(bm + lr) * K + lc;
    const float* Bptr = B + (size_t)(bn + lr) * K + lc;
    const float4 zero4 = make_float4(0.f, 0.f, 0.f, 0.f);

    for (int k0 = 0; k0 < K; k0 += 8) {
        float4 a4 = aval ? *(const float4*)(Aptr + k0) : zero4;
        float4 b4 = bval ? *(const float4*)(Bptr + k0) : zero4;
        As[lc + 0][lr] = a4.x; As[lc + 1][lr] = a4.y;
        As[lc + 2][lr] = a4.z; As[lc + 3][lr] = a4.w;
        Bs[lc + 0][lr] = b4.x; Bs[lc + 1][lr] = b4.y;
        Bs[lc + 2][lr] = b4.z; Bs[lc + 3][lr] = b4.w;
        __syncthreads();
        #pragma unroll
        for (int kk = 0; kk < 8; kk++) {
            float ra[8], rb[8];
            *(float4*)(ra)     = *(const float4*)(&As[kk][ty * 8]);
            *(float4*)(ra + 4) = *(const float4*)(&As[kk][ty * 8 + 4]);
            *(float4*)(rb)     = *(const float4*)(&Bs[kk][tx * 8]);
            *(float4*)(rb + 4) = *(const float4*)(&Bs[kk][tx * 8 + 4]);
            #pragma unroll
            for (int i = 0; i < 8; i++)
                #pragma unroll
                for (int j = 0; j < 8; j++)
                    acc[i][j] += ra[i] * rb[j];
        }
        __syncthreads();
    }

    #pragma unroll
    for (int i = 0; i < 8; i++) {
        int row = bm + ty * 8 + i;
        if (row >= M) continue;
        #pragma unroll
        for (int j = 0; j < 8; j++) {
            int col = bn + tx * 8 + j;
            if (col >= N) continue;
            float v = acc[i][j];
            if (bias1) v += bias1[col];
            if (bias2) v += bias2[col];
            if (res)   v += res[(size_t)row * N + col];
            C[(size_t)row * N + col] = v;
        }
    }
}

// ---------------- persistent LSTM: all 127 steps in one kernel ----------------
// 128 blocks x 256 threads. Block j owns h-columns [4j, 4j+4) -> 16 gate rows.
// w_hh slice lives in smem for the whole kernel; cell state lives in registers.
// Grid barrier between steps (all 128 blocks are co-resident: 1 block/SM).
#define HP 516   // h smem pitch (floats)
#define WP 516   // w smem pitch (floats)
__global__ __launch_bounds__(256) void lstm_persistent_kernel(
    const float* __restrict__ xg, const float* __restrict__ w_hh,
    float* __restrict__ hbuf0, float* __restrict__ hbuf1,
    float* __restrict__ lstm_out)
{
    extern __shared__ float smem[];
    float* h_sm = smem;                    // 32 * HP
    float* w_sm = smem + 32 * HP;          // 16 * WP
    float* g_sm = w_sm + 16 * WP;          // 16 * 33

    const int tid = threadIdx.x;
    const int c0  = blockIdx.x * 4;

    // Load 16 w_hh rows (4 gates x 4 cols) once for the entire kernel.
    for (int idx = tid; idx < 16 * 128; idx += 256) {
        int r = idx >> 7; int k4 = (idx & 127) << 2;
        int gr = (r >> 2) * HH + c0 + (r & 3);
        float4 v = *(const float4*)(w_hh + (size_t)gr * HH + k4);
        float* d = w_sm + r * WP + k4;
        d[0] = v.x; d[1] = v.y; d[2] = v.z; d[3] = v.w;
    }

    // compute mapping: 2 batches x 1 gate-row per thread
    const int bp = tid >> 4;          // 0..15 batch pair
    const int cc = tid & 15;          // gate row within block (q*4+lc)
    const int q  = cc >> 2;
    const int lc = cc & 3;
    const int col = q * HH + c0 + lc; // column into xg's 2048
    const int b0 = 2 * bp, b1 = b0 + 1;
    const float* h0 = h_sm + b0 * HP;
    const float* h1 = h_sm + b1 * HP;
    const float* wrow = w_sm + cc * WP;

    // activation mapping (tid < 128): col acc_c, batch acc_b; c state in register
    const int acc_c = tid & 3;
    const int acc_b = tid >> 2;
    float c_reg = 0.f;

    for (int t = 0; t < TT; t++) {
        const float* hprev = (t & 1) ? hbuf1 : hbuf0;
        float*       hnext = (t & 1) ? hbuf0 : hbuf1;

        // stage h_prev [32,512] -> smem (bypass L1: buffer is rewritten every 2 steps)
        __syncthreads();   // protect h_sm from previous iteration's readers
        for (int idx = tid; idx < 32 * 128; idx += 256) {
            int b = idx >> 7; int k4 = (idx & 127) << 2;
            float4 v = __ldcg((const float4*)(hprev + b * HH + k4));
            float* d = h_sm + b * HP + k4;
            d[0] = v.x; d[1] = v.y; d[2] = v.z; d[3] = v.w;
        }
        __syncthreads();

        // gates = h_prev @ w_hh^T (2 batches x 1 row per thread)
        float a0 = 0.f, a1 = 0.f;
        #pragma unroll 8
        for (int k = 0; k < HH; k += 4) {
            float4 wv = *(const float4*)(wrow + k);
            float4 x0 = *(const float4*)(h0 + k);
            float4 x1 = *(const float4*)(h1 + k);
            a0 += x0.x * wv.x; a1 += x1.x * wv.x;
            a0 += x0.y * wv.y; a1 += x1.y * wv.y;
            a0 += x0.z * wv.z; a1 += x1.z * wv.z;
            a0 += x0.w * wv.w; a1 += x1.w * wv.w;
        }
        g_sm[cc * 33 + b0] = a0 + xg[(size_t)(b0 * TT + t) * (4 * HH) + col];
        g_sm[cc * 33 + b1] = a1 + xg[(size_t)(b1 * TT + t) * (4 * HH) + col];
        __syncthreads();

        // activations + state update (128 threads: 4 cols x 32 batches)
        if (tid < 128) {
            float iv = g_sm[(0  + acc_c) * 33 + acc_b];
            float fv = g_sm[(4  + acc_c) * 33 + acc_b];
            float gv = g_sm[(8  + acc_c) * 33 + acc_b];
            float ov = g_sm[(12 + acc_c) * 33 + acc_b];
            float ig = 1.f / (1.f + __expf(-iv));
            float fg = 1.f / (1.f + __expf(-fv));
            float og = 1.f / (1.f + __expf(-ov));
            float gg = tanhf(gv);
            c_reg = fg * c_reg + ig * gg;
            float hn = og * tanhf(c_reg);
            hnext[acc_b * HH + c0 + acc_c] = hn;
            lstm_out[(size_t)(acc_b * TT + t) * HH + c0 + acc_c] = hn;
        }
        __threadfence();
        __syncthreads();

        // grid barrier: all blocks done with step t
        if (tid == 0) {
            atomicAdd((unsigned*)&g_bar, 1u);
            unsigned target = (unsigned)(t + 1) * NBLK;
            while (g_bar < target) { }
        }
        __syncthreads();
    }
}

// ---------------- fused attention: per (t-chunk, head, batch) ----------------
#define KTP 257   // transposed K/V pitch (257 mod 32 == 1 -> conflict-free lane stride)
#define QSP 68
#define PSP 260
__global__ __launch_bounds__(256) void attn_kernel(
    const float* __restrict__ q, const float* __restrict__ kmat,
    const float* __restrict__ vmat, float* __restrict__ ctx)
{
    extern __shared__ float smem[];
    float* Kt   = smem;                    // [64][KTP]
    float* Vt   = Kt + 64 * KTP;           // [64][KTP]
    float* qs   = Vt + 64 * KTP;           // [32][QSP]
    float* ps   = qs + 32 * QSP;           // [32][PSP]
    float* sums = ps + 32 * PSP;           // [32]

    const int t0 = blockIdx.x * 32;
    const int h  = blockIdx.y;
    const int b  = blockIdx.z;
    const int tid = threadIdx.x;

    // load K,V transposed: Kt[d][s] = K[b*256+s][h*64+d]
    for (int idx = tid; idx < 256 * 16; idx += 256) {
        int s = idx >> 4; int d4 = (idx & 15) << 2;
        size_t off = (size_t)(b * SS + s) * HH + h * HDD + d4;
        float4 kv = *(const float4*)(kmat + off);
        Kt[(d4 + 0) * KTP + s] = kv.x; Kt[(d4 + 1) * KTP + s] = kv.y;
        Kt[(d4 + 2) * KTP + s] = kv.z; Kt[(d4 + 3) * KTP + s] = kv.w;
        float4 vv = *(const float4*)(vmat + off);
        Vt[(d4 + 0) * KTP + s] = vv.x; Vt[(d4 + 1) * KTP + s] = vv.y;
        Vt[(d4 + 2) * KTP + s] = vv.z; Vt[(d4 + 3) * KTP + s] = vv.w;
    }
    // load q chunk
    for (int idx = tid; idx < 32 * 16; idx += 256) {
        int r = idx >> 4; int d4 = (idx & 15) << 2;
        int trow = t0 + r;
        float4 qv = make_float4(0.f, 0.f, 0.f, 0.f);
        if (trow < TT)
            qv = *(const float4*)(q + (size_t)(b * TT + trow) * HH + h * HDD + d4);
        float* d = qs + r * QSP + d4;
        d[0] = qv.x; d[1] = qv.y; d[2] = qv.z; d[3] = qv.w;
    }
    __syncthreads();

    const int r  = tid >> 3;  // query row in chunk
    const int lc = tid & 7;   // lane-col

    float qreg[64];
    #pragma unroll
    for (int d = 0; d < 64; d++) qreg[d] = qs[r * QSP + d];

    float sc[32];
    for (int si = 0; si < 32; si++) {
        int s = si * 8 + lc;
        float acc = 0.f;
        #pragma unroll
        for (int d = 0; d < 64; d++) acc += qreg[d] * Kt[d * KTP + s];
        sc[si] = acc * 0.125f;   // 1/sqrt(64)
    }
    float m = -1e30f;
    #pragma unroll
    for (int si = 0; si < 32; si++) m = fmaxf(m, sc[si]);
    m = fmaxf(m, __shfl_xor_sync(0xffffffff, m, 1));
    m = fmaxf(m, __shfl_xor_sync(0xffffffff, m, 2));
    m = fmaxf(m, __shfl_xor_sync(0xffffffff, m, 4));
    float ssum = 0.f;
    #pragma unroll
    for (int si = 0; si < 32; si++) {
        float e = __expf(sc[si] - m);
        ssum += e;
        ps[r * PSP + si * 8 + lc] = e;
    }
    ssum += __shfl_xor_sync(0xffffffff, ssum, 1);
    ssum += __shfl_xor_sync(0xffffffff, ssum, 2);
    ssum += __shfl_xor_sync(0xffffffff, ssum, 4);
    if (lc == 0) sums[r] = ssum;
    __syncthreads();

    // ctx: thread covers d = lc + 8j
    float accv[8];
    #pragma unroll
    for (int j = 0; j < 8; j++) accv[j] = 0.f;
    const float* prow = ps + r * PSP;
    #pragma unroll 4
    for (int s = 0; s < 256; s++) {
        float pv = prow[s];
        #pragma unroll
        for (int j = 0; j < 8; j++)
            accv[j] += pv * Vt[(lc + 8 * j) * KTP + s];
    }
    float inv = 1.0f / sums[r];
    int trow = t0 + r;
    if (trow < TT) {
        float* dst = ctx + (size_t)(b * TT + trow) * HH + h * HDD;
        #pragma unroll
        for (int j = 0; j < 8; j++) dst[lc + 8 * j] = accv[j] * inv;
    }
}

// ---------------- launch ----------------
extern "C" void kernel_launch(void* const* d_in, const int* in_sizes, int n_in,
                              void* d_out, int out_size) {
    const int*   targets  = (const int*)  d_in[0];
    const float* enc      = (const float*)d_in[1];
    const float* embedding= (const float*)d_in[2];
    const float* w_ih     = (const float*)d_in[3];
    const float* w_hh     = (const float*)d_in[4];
    const float* b_ih     = (const float*)d_in[5];
    const float* b_hh     = (const float*)d_in[6];
    const float* in_proj_w= (const float*)d_in[7];
    const float* in_proj_b= (const float*)d_in[8];
    const float* out_proj_w=(const float*)d_in[9];
    const float* out_proj_b=(const float*)d_in[10];
    const float* fc_w     = (const float*)d_in[11];
    const float* fc_b     = (const float*)d_in[12];
    float* out = (float*)d_out;

    float *p_emb, *p_xg, *p_h, *p_lstm, *p_q, *p_k, *p_v, *p_ctx, *p_comb;
    cudaGetSymbolAddress((void**)&p_emb,  g_emb);
    cudaGetSymbolAddress((void**)&p_xg,   g_xg);
    cudaGetSymbolAddress((void**)&p_h,    g_h);
    cudaGetSymbolAddress((void**)&p_lstm, g_lstm);
    cudaGetSymbolAddress((void**)&p_q,    g_q);
    cudaGetSymbolAddress((void**)&p_k,    g_k);
    cudaGetSymbolAddress((void**)&p_v,    g_v);
    cudaGetSymbolAddress((void**)&p_ctx,  g_ctx);
    cudaGetSymbolAddress((void**)&p_comb, g_comb);
    float* h_buf0 = p_h;
    float* h_buf1 = p_h + BB * HH;

    const int lstm_smem = (32 * HP + 16 * WP + 16 * 33) * (int)sizeof(float);
    const int attn_smem = (64 * KTP * 2 + 32 * QSP + 32 * PSP + 32) * (int)sizeof(float);
    cudaFuncSetAttribute(lstm_persistent_kernel, cudaFuncAttributeMaxDynamicSharedMemorySize, lstm_smem);
    cudaFuncSetAttribute(attn_kernel,            cudaFuncAttributeMaxDynamicSharedMemorySize, attn_smem);

    // 1. zero h0 + barrier counter
    zero_kernel<<<(BB * HH + 255) / 256, 256>>>(h_buf0, BB * HH);

    // 2. gather embeddings
    gather_kernel<<<BT, 128>>>(targets, embedding, p_emb);

    // 3. xg = emb @ w_ih^T + b_ih + b_hh   [4064, 2048]
    {
        dim3 grid((4 * HH + 127) / 128, (BT + 127) / 128);
        sgemm_kernel<<<grid, 256>>>(p_emb, w_ih, b_ih, b_hh, nullptr, p_xg, BT, 4 * HH, HH);
    }

    // 4. LSTM recurrence — one persistent kernel for all 127 steps
    lstm_persistent_kernel<<<NBLK, 256, lstm_smem>>>(p_xg, w_hh, h_buf0, h_buf1, p_lstm);

    // 5. q/k/v projections
    {
        dim3 gq((HH + 127) / 128, (BT + 127) / 128);
        sgemm_kernel<<<gq, 256>>>(p_lstm, in_proj_w, in_proj_b, nullptr, nullptr, p_q, BT, HH, HH);
        dim3 gk((HH + 127) / 128, (BS + 127) / 128);
        sgemm_kernel<<<gk, 256>>>(enc, in_proj_w + (size_t)HH * HH, in_proj_b + HH,
                                  nullptr, nullptr, p_k, BS, HH, HH);
        sgemm_kernel<<<gk, 256>>>(enc, in_proj_w + (size_t)2 * HH * HH, in_proj_b + 2 * HH,
                                  nullptr, nullptr, p_v, BS, HH, HH);
    }

    // 6. fused attention -> ctx
    {
        dim3 grid(4, NHH, BB);
        attn_kernel<<<grid, 256, attn_smem>>>(p_q, p_k, p_v, p_ctx);
    }

    // 7. combined = ctx @ out_proj^T + out_proj_b + lstm_out
    {
        dim3 grid((HH + 127) / 128, (BT + 127) / 128);
        sgemm_kernel<<<grid, 256>>>(p_ctx, out_proj_w, out_proj_b, nullptr, p_lstm, p_comb, BT, HH, HH);
    }

    // 8. out = combined @ fc_w^T + fc_b   [4064, 8000]
    {
        dim3 grid((VV + 127) / 128, (BT + 127) / 128);
        sgemm_kernel<<<grid, 256>>>(p_comb, fc_w, fc_b, nullptr, nullptr, out, BT, VV, HH);
    }
}

// round 3
// speedup vs baseline: 1.3391x; 1.0295x over previous
#include <cuda_runtime.h>
#include <cuda_bf16.h>
#include <math.h>

// Problem constants
#define BB   32
#define TT   127
#define SS   256
#define HH   512
#define VV   8000
#define NHH  8
#define HDD  64
#define BT   (BB*TT)      // 4064
#define BS   (BB*SS)      // 8192
#define NBLK 128          // persistent LSTM grid (must all be co-resident)

// ---------------- scratch (device globals; no allocations allowed) ----------------
__device__ float g_emb [BT * HH];        // embedded targets
__device__ float g_xg  [BT * 4 * HH];    // precomputed input gates
__device__ float g_h   [2][BB * HH];     // ping-pong hidden state
__device__ float g_lstm[BT * HH];        // lstm outputs
__device__ float g_q   [BT * HH];
__device__ float g_k   [BS * HH];
__device__ float g_v   [BS * HH];
__device__ float g_ctx [BT * HH];
__device__ float g_comb[BT * HH];
__device__ volatile unsigned g_bar;      // grid barrier counter

// ---------------- cp.async helpers ----------------
__device__ __forceinline__ void cp_async16(float* dst_smem, const float* src_gmem) {
    unsigned s = (unsigned)__cvta_generic_to_shared(dst_smem);
    asm volatile("cp.async.cg.shared.global [%0], [%1], 16;\n" :: "r"(s), "l"(src_gmem));
}
__device__ __forceinline__ void cp_async_commit() { asm volatile("cp.async.commit_group;\n"); }
__device__ __forceinline__ void cp_async_wait0()  { asm volatile("cp.async.wait_group 0;\n"); }

// ---------------- init: zero h0 and barrier ----------------
__global__ void zero_kernel(float* h0, int n) {
    int i = blockIdx.x * blockDim.x + threadIdx.x;
    if (i < n) h0[i] = 0.f;
    if (i == 0) g_bar = 0u;
}

// ---------------- embedding gather ----------------
__global__ void gather_kernel(const int* __restrict__ targets,
                              const float* __restrict__ table,
                              float* __restrict__ out) {
    int bt = blockIdx.x;                 // 0..4063
    int b = bt / TT, t = bt - b * TT;
    int tok = targets[b * 128 + t];      // targets is [B,128], use [:, :-1]
    const float4* src = (const float4*)(table + (size_t)tok * HH);
    float4* dst = (float4*)(out + (size_t)bt * HH);
    dst[threadIdx.x] = src[threadIdx.x]; // 128 threads * float4 = 512 floats
}

// ---------------- generic SGEMM: C[M,N] = A[M,K] @ B[N,K]^T + bias1 + bias2 + res ----------------
__global__ __launch_bounds__(256) void sgemm_kernel(
    const float* __restrict__ A, const float* __restrict__ B,
    const float* __restrict__ bias1, const float* __restrict__ bias2,
    const float* __restrict__ res, float* __restrict__ C,
    int M, int N, int K)
{
    __shared__ float As[8][128];
    __shared__ float Bs[8][128];
    const int bm = blockIdx.y * 128;
    const int bn = blockIdx.x * 128;
    const int tid = threadIdx.x;
    const int lr = tid >> 1;            // 0..127 (load row)
    const int lc = (tid & 1) << 2;      // 0 or 4 (load col group)
    const int tx = tid & 15;            // n-tile
    const int ty = tid >> 4;            // m-tile

    float acc[8][8];
    #pragma unroll
    for (int i = 0; i < 8; i++)
        #pragma unroll
        for (int j = 0; j < 8; j++) acc[i][j] = 0.f;

    const bool aval = (bm + lr) < M;
    const bool bval = (bn + lr) < N;
    const float* Aptr = A + (size_t)(bm + lr) * K + lc;
    const float* Bptr = B + (size_t)(bn + lr) * K + lc;
    const float4 zero4 = make_float4(0.f, 0.f, 0.f, 0.f);

    for (int k0 = 0; k0 < K; k0 += 8) {
        float4 a4 = aval ? *(const float4*)(Aptr + k0) : zero4;
        float4 b4 = bval ? *(const float4*)(Bptr + k0) : zero4;
        As[lc + 0][lr] = a4.x; As[lc + 1][lr] = a4.y;
        As[lc + 2][lr] = a4.z; As[lc + 3][lr] = a4.w;
        Bs[lc + 0][lr] = b4.x; Bs[lc + 1][lr] = b4.y;
        Bs[lc + 2][lr] = b4.z; Bs[lc + 3][lr] = b4.w;
        __syncthreads();
        #pragma unroll
        for (int kk = 0; kk < 8; kk++) {
            float ra[8], rb[8];
            *(float4*)(ra)     = *(const float4*)(&As[kk][ty * 8]);
            *(float4*)(ra + 4) = *(const float4*)(&As[kk][ty * 8 + 4]);
            *(float4*)(rb)     = *(const float4*)(&Bs[kk][tx * 8]);
            *(float4*)(rb + 4) = *(const float4*)(&Bs[kk][tx * 8 + 4]);
            #pragma unroll
            for (int i = 0; i < 8; i++)
                #pragma unroll
                for (int j = 0; j < 8; j++)
                    acc[i][j] += ra[i] * rb[j];
        }
        __syncthreads();
    }

    #pragma unroll
    for (int i = 0; i < 8; i++) {
        int row = bm + ty * 8 + i;
        if (row >= M) continue;
        #pragma unroll
        for (int j = 0; j < 8; j++) {
            int col = bn + tx * 8 + j;
            if (col >= N) continue;
            float v = acc[i][j];
            if (bias1) v += bias1[col];
            if (bias2) v += bias2[col];
            if (res)   v += res[(size_t)row * N + col];
            C[(size_t)row * N + col] = v;
        }
    }
}

// ---------------- persistent LSTM: all 127 steps in one kernel ----------------
// 128 blocks x 256 threads. Block j owns h-columns [4j, 4j+4) -> 16 gate rows.
// w_hh slice lives in smem for the whole kernel; cell state lives in registers.
// Grid barrier between steps (all 128 blocks are co-resident: 1 block/SM).
#define HP 516   // h smem pitch (floats)
#define WP 516   // w smem pitch (floats)
__global__ __launch_bounds__(256) void lstm_persistent_kernel(
    const float* __restrict__ xg, const float* __restrict__ w_hh,
    float* __restrict__ hbuf0, float* __restrict__ hbuf1,
    float* __restrict__ lstm_out)
{
    extern __shared__ float smem[];
    float* h_sm = smem;                    // 32 * HP
    float* w_sm = smem + 32 * HP;          // 16 * WP
    float* g_sm = w_sm + 16 * WP;          // 16 * 33

    const int tid = threadIdx.x;
    const int c0  = blockIdx.x * 4;

    // Load 16 w_hh rows (4 gates x 4 cols) once for the entire kernel.
    for (int idx = tid; idx < 16 * 128; idx += 256) {
        int r = idx >> 7; int k4 = (idx & 127) << 2;
        int gr = (r >> 2) * HH + c0 + (r & 3);
        float4 v = *(const float4*)(w_hh + (size_t)gr * HH + k4);
        float* d = w_sm + r * WP + k4;
        d[0] = v.x; d[1] = v.y; d[2] = v.z; d[3] = v.w;
    }

    // compute mapping: 2 batches x 1 gate-row per thread
    const int bp = tid >> 4;          // 0..15 batch pair
    const int cc = tid & 15;          // gate row within block (q*4+lc)
    const int q  = cc >> 2;
    const int lc = cc & 3;
    const int col = q * HH + c0 + lc; // column into xg's 2048
    const int b0 = 2 * bp, b1 = b0 + 1;
    const float* h0 = h_sm + b0 * HP;
    const float* h1 = h_sm + b1 * HP;
    const float* wrow = w_sm + cc * WP;
    const size_t xgr0 = (size_t)(b0 * TT) * (4 * HH) + col;
    const size_t xgr1 = (size_t)(b1 * TT) * (4 * HH) + col;

    // activation mapping (tid < 128): col acc_c, batch acc_b; c state in register
    const int acc_c = tid & 3;
    const int acc_b = tid >> 2;
    float c_reg = 0.f;

    for (int t = 0; t < TT; t++) {
        const float* hprev = (t & 1) ? hbuf1 : hbuf0;
        float*       hnext = (t & 1) ? hbuf0 : hbuf1;

        // stage h_prev [32,512] -> smem via cp.async (L2-only, MLP from async unit)
        __syncthreads();   // protect h_sm from previous iteration's readers
        #pragma unroll
        for (int i = 0; i < 16; i++) {
            int idx = tid + i * 256;              // 0..4095
            int b = idx >> 7; int k4 = (idx & 127) << 2;
            cp_async16(h_sm + b * HP + k4, hprev + b * HH + k4);
        }
        cp_async_commit();

        // prefetch xg for this step while the copy is in flight
        float x0 = __ldg(xg + xgr0 + (size_t)t * (4 * HH));
        float x1 = __ldg(xg + xgr1 + (size_t)t * (4 * HH));

        cp_async_wait0();
        __syncthreads();

        // gates = h_prev @ w_hh^T : 2 batches x 1 row, 4 independent FMA chains
        float a00 = 0.f, a01 = 0.f, a10 = 0.f, a11 = 0.f;
        #pragma unroll 4
        for (int k = 0; k < HH; k += 8) {
            float4 w0 = *(const float4*)(wrow + k);
            float4 w1 = *(const float4*)(wrow + k + 4);
            float4 p0 = *(const float4*)(h0 + k);
            float4 p1 = *(const float4*)(h0 + k + 4);
            float4 r0 = *(const float4*)(h1 + k);
            float4 r1 = *(const float4*)(h1 + k + 4);
            a00 = fmaf(w0.x, p0.x, a00); a00 = fmaf(w0.y, p0.y, a00);
            a00 = fmaf(w0.z, p0.z, a00); a00 = fmaf(w0.w, p0.w, a00);
            a01 = fmaf(w1.x, p1.x, a01); a01 = fmaf(w1.y, p1.y, a01);
            a01 = fmaf(w1.z, p1.z, a01); a01 = fmaf(w1.w, p1.w, a01);
            a10 = fmaf(w0.x, r0.x, a10); a10 = fmaf(w0.y, r0.y, a10);
            a10 = fmaf(w0.z, r0.z, a10); a10 = fmaf(w0.w, r0.w, a10);
            a11 = fmaf(w1.x, r1.x, a11); a11 = fmaf(w1.y, r1.y, a11);
            a11 = fmaf(w1.z, r1.z, a11); a11 = fmaf(w1.w, r1.w, a11);
        }
        g_sm[cc * 33 + b0] = (a00 + a01) + x0;
        g_sm[cc * 33 + b1] = (a10 + a11) + x1;
        __syncthreads();

        // activations + state update (128 threads: 4 cols x 32 batches)
        if (tid < 128) {
            float iv = g_sm[(0  + acc_c) * 33 + acc_b];
            float fv = g_sm[(4  + acc_c) * 33 + acc_b];
            float gv = g_sm[(8  + acc_c) * 33 + acc_b];
            float ov = g_sm[(12 + acc_c) * 33 + acc_b];
            float ig = 1.f / (1.f + __expf(-iv));
            float fg = 1.f / (1.f + __expf(-fv));
            float og = 1.f / (1.f + __expf(-ov));
            float gg = tanhf(gv);
            c_reg = fg * c_reg + ig * gg;
            float hn = og * tanhf(c_reg);
            hnext[acc_b * HH + c0 + acc_c] = hn;
            lstm_out[(size_t)(acc_b * TT + t) * HH + c0 + acc_c] = hn;
        }
        __threadfence();
        __syncthreads();

        // grid barrier: all blocks done with step t
        if (tid == 0) {
            atomicAdd((unsigned*)&g_bar, 1u);
            unsigned target = (unsigned)(t + 1) * NBLK;
            while (g_bar < target) { }
        }
        __syncthreads();
    }
}

// ---------------- fused attention: per (t-chunk, head, batch) ----------------
#define KTP 257   // transposed K/V pitch (257 mod 32 == 1 -> conflict-free lane stride)
#define QSP 68
#define PSP 260
__global__ __launch_bounds__(256) void attn_kernel(
    const float* __restrict__ q, const float* __restrict__ kmat,
    const float* __restrict__ vmat, float* __restrict__ ctx)
{
    extern __shared__ float smem[];
    float* Kt   = smem;                    // [64][KTP]
    float* Vt   = Kt + 64 * KTP;           // [64][KTP]
    float* qs   = Vt + 64 * KTP;           // [32][QSP]
    float* ps   = qs + 32 * QSP;           // [32][PSP]
    float* sums = ps + 32 * PSP;           // [32]

    const int t0 = blockIdx.x * 32;
    const int h  = blockIdx.y;
    const int b  = blockIdx.z;
    const int tid = threadIdx.x;

    // load K,V transposed: Kt[d][s] = K[b*256+s][h*64+d]
    for (int idx = tid; idx < 256 * 16; idx += 256) {
        int s = idx >> 4; int d4 = (idx & 15) << 2;
        size_t off = (size_t)(b * SS + s) * HH + h * HDD + d4;
        float4 kv = *(const float4*)(kmat + off);
        Kt[(d4 + 0) * KTP + s] = kv.x; Kt[(d4 + 1) * KTP + s] = kv.y;
        Kt[(d4 + 2) * KTP + s] = kv.z; Kt[(d4 + 3) * KTP + s] = kv.w;
        float4 vv = *(const float4*)(vmat + off);
        Vt[(d4 + 0) * KTP + s] = vv.x; Vt[(d4 + 1) * KTP + s] = vv.y;
        Vt[(d4 + 2) * KTP + s] = vv.z; Vt[(d4 + 3) * KTP + s] = vv.w;
    }
    // load q chunk
    for (int idx = tid; idx < 32 * 16; idx += 256) {
        int r = idx >> 4; int d4 = (idx & 15) << 2;
        int trow = t0 + r;
        float4 qv = make_float4(0.f, 0.f, 0.f, 0.f);
        if (trow < TT)
            qv = *(const float4*)(q + (size_t)(b * TT + trow) * HH + h * HDD + d4);
        float* d = qs + r * QSP + d4;
        d[0] = qv.x; d[1] = qv.y; d[2] = qv.z; d[3] = qv.w;
    }
    __syncthreads();

    const int r  = tid >> 3;  // query row in chunk
    const int lc = tid & 7;   // lane-col

    float qreg[64];
    #pragma unroll
    for (int d = 0; d < 64; d++) qreg[d] = qs[r * QSP + d];

    float sc[32];
    for (int si = 0; si < 32; si++) {
        int s = si * 8 + lc;
        float acc = 0.f;
        #pragma unroll
        for (int d = 0; d < 64; d++) acc += qreg[d] * Kt[d * KTP + s];
        sc[si] = acc * 0.125f;   // 1/sqrt(64)
    }
    float m = -1e30f;
    #pragma unroll
    for (int si = 0; si < 32; si++) m = fmaxf(m, sc[si]);
    m = fmaxf(m, __shfl_xor_sync(0xffffffff, m, 1));
    m = fmaxf(m, __shfl_xor_sync(0xffffffff, m, 2));
    m = fmaxf(m, __shfl_xor_sync(0xffffffff, m, 4));
    float ssum = 0.f;
    #pragma unroll
    for (int si = 0; si < 32; si++) {
        float e = __expf(sc[si] - m);
        ssum += e;
        ps[r * PSP + si * 8 + lc] = e;
    }
    ssum += __shfl_xor_sync(0xffffffff, ssum, 1);
    ssum += __shfl_xor_sync(0xffffffff, ssum, 2);
    ssum += __shfl_xor_sync(0xffffffff, ssum, 4);
    if (lc == 0) sums[r] = ssum;
    __syncthreads();

    // ctx: thread covers d = lc + 8j
    float accv[8];
    #pragma unroll
    for (int j = 0; j < 8; j++) accv[j] = 0.f;
    const float* prow = ps + r * PSP;
    #pragma unroll 4
    for (int s = 0; s < 256; s++) {
        float pv = prow[s];
        #pragma unroll
        for (int j = 0; j < 8; j++)
            accv[j] += pv * Vt[(lc + 8 * j) * KTP + s];
    }
    float inv = 1.0f / sums[r];
    int trow = t0 + r;
    if (trow < TT) {
        float* dst = ctx + (size_t)(b * TT + trow) * HH + h * HDD;
        #pragma unroll
        for (int j = 0; j < 8; j++) dst[lc + 8 * j] = accv[j] * inv;
    }
}

// ---------------- launch ----------------
extern "C" void kernel_launch(void* const* d_in, const int* in_sizes, int n_in,
                              void* d_out, int out_size) {
    const int*   targets  = (const int*)  d_in[0];
    const float* enc      = (const float*)d_in[1];
    const float* embedding= (const float*)d_in[2];
    const float* w_ih     = (const float*)d_in[3];
    const float* w_hh     = (const float*)d_in[4];
    const float* b_ih     = (const float*)d_in[5];
    const float* b_hh     = (const float*)d_in[6];
    const float* in_proj_w= (const float*)d_in[7];
    const float* in_proj_b= (const float*)d_in[8];
    const float* out_proj_w=(const float*)d_in[9];
    const float* out_proj_b=(const float*)d_in[10];
    const float* fc_w     = (const float*)d_in[11];
    const float* fc_b     = (const float*)d_in[12];
    float* out = (float*)d_out;

    float *p_emb, *p_xg, *p_h, *p_lstm, *p_q, *p_k, *p_v, *p_ctx, *p_comb;
    cudaGetSymbolAddress((void**)&p_emb,  g_emb);
    cudaGetSymbolAddress((void**)&p_xg,   g_xg);
    cudaGetSymbolAddress((void**)&p_h,    g_h);
    cudaGetSymbolAddress((void**)&p_lstm, g_lstm);
    cudaGetSymbolAddress((void**)&p_q,    g_q);
    cudaGetSymbolAddress((void**)&p_k,    g_k);
    cudaGetSymbolAddress((void**)&p_v,    g_v);
    cudaGetSymbolAddress((void**)&p_ctx,  g_ctx);
    cudaGetSymbolAddress((void**)&p_comb, g_comb);
    float* h_buf0 = p_h;
    float* h_buf1 = p_h + BB * HH;

    const int lstm_smem = (32 * HP + 16 * WP + 16 * 33) * (int)sizeof(float);
    const int attn_smem = (64 * KTP * 2 + 32 * QSP + 32 * PSP + 32) * (int)sizeof(float);
    cudaFuncSetAttribute(lstm_persistent_kernel, cudaFuncAttributeMaxDynamicSharedMemorySize, lstm_smem);
    cudaFuncSetAttribute(attn_kernel,            cudaFuncAttributeMaxDynamicSharedMemorySize, attn_smem);

    // 1. zero h0 + barrier counter
    zero_kernel<<<(BB * HH + 255) / 256, 256>>>(h_buf0, BB * HH);

    // 2. gather embeddings
    gather_kernel<<<BT, 128>>>(targets, embedding, p_emb);

    // 3. xg = emb @ w_ih^T + b_ih + b_hh   [4064, 2048]
    {
        dim3 grid((4 * HH + 127) / 128, (BT + 127) / 128);
        sgemm_kernel<<<grid, 256>>>(p_emb, w_ih, b_ih, b_hh, nullptr, p_xg, BT, 4 * HH, HH);
    }

    // 4. LSTM recurrence — one persistent kernel for all 127 steps
    lstm_persistent_kernel<<<NBLK, 256, lstm_smem>>>(p_xg, w_hh, h_buf0, h_buf1, p_lstm);

    // 5. q/k/v projections
    {
        dim3 gq((HH + 127) / 128, (BT + 127) / 128);
        sgemm_kernel<<<gq, 256>>>(p_lstm, in_proj_w, in_proj_b, nullptr, nullptr, p_q, BT, HH, HH);
        dim3 gk((HH + 127) / 128, (BS + 127) / 128);
        sgemm_kernel<<<gk, 256>>>(enc, in_proj_w + (size_t)HH * HH, in_proj_b + HH,
                                  nullptr, nullptr, p_k, BS, HH, HH);
        sgemm_kernel<<<gk, 256>>>(enc, in_proj_w + (size_t)2 * HH * HH, in_proj_b + 2 * HH,
                                  nullptr, nullptr, p_v, BS, HH, HH);
    }

    // 6. fused attention -> ctx
    {
        dim3 grid(4, NHH, BB);
        attn_kernel<<<grid, 256, attn_smem>>>(p_q, p_k, p_v, p_ctx);
    }

    // 7. combined = ctx @ out_proj^T + out_proj_b + lstm_out
    {
        dim3 grid((HH + 127) / 128, (BT + 127) / 128);
        sgemm_kernel<<<grid, 256>>>(p_ctx, out_proj_w, out_proj_b, nullptr, p_lstm, p_comb, BT, HH, HH);
    }

    // 8. out = combined @ fc_w^T + fc_b   [4064, 8000]
    {
        dim3 grid((VV + 127) / 128, (BT + 127) / 128);
        sgemm_kernel<<<grid, 256>>>(p_comb, fc_w, fc_b, nullptr, nullptr, out, BT, VV, HH);
    }
}